// round 8
// baseline (speedup 1.0000x reference)
#include <cuda_runtime.h>
#include <cuda_bf16.h>
#include <math.h>
#include <stdint.h>

// ---------------------------------------------------------------------------
// SwinTransformerBlock3D  (B=4, D=8, H=56, W=56, C=128, WIN=(2,7,7), HEADS=4)
// ---------------------------------------------------------------------------

#define M_TOK 100352            // 4*8*56*56 == 1024 windows * 98 tokens

__device__ __nv_bfloat16 g_qkv[(size_t)M_TOK*384];   // qkv, window order
__device__ __nv_bfloat16 g_ao [(size_t)M_TOK*128];   // attn out, window order
__device__ float         g_y2 [(size_t)M_TOK*128];   // x + proj (spatial)
__device__ __nv_bfloat16 g_wt [196608];              // bf16 weights
__device__ __nv_bfloat16 g_btab[4*98*112];           // bf16(log2e * rpb[rel_idx])

// window row r -> spatial token (roll -SHIFT folded in); self-inverse mapping.
__device__ __forceinline__ int win_row_to_token(int r) {
    int win = r / 98;
    int n   = r - win * 98;
    int ww = win & 7;
    int wh = (win >> 3) & 7;
    int wd = (win >> 6) & 3;
    int b  = win >> 8;
    int id  = n / 49;
    int rem = n - id * 49;
    int ih  = rem / 7;
    int iw  = rem - ih * 7;
    int d = wd * 2 + id;
    int h = wh * 7 + ih;
    int w = ww * 7 + iw;
    int ds = d + 1;  if (ds >= 8)  ds -= 8;
    int hs = h + 3;  if (hs >= 56) hs -= 56;
    int ws = w + 3;  if (ws >= 56) ws -= 56;
    return ((b * 8 + ds) * 56 + hs) * 56 + ws;
}

// ---------------------------------------------------------------------------
// helpers
// ---------------------------------------------------------------------------
__device__ __forceinline__ uint32_t cvta_smem(const void* p) {
    uint32_t a;
    asm("{ .reg .u64 t; cvta.to.shared.u64 t, %1; cvt.u32.u64 %0, t; }"
        : "=r"(a) : "l"(p));
    return a;
}
__device__ __forceinline__ uint32_t packbf(float a, float b) {
    __nv_bfloat162 t = __floats2bfloat162_rn(a, b);
    return *reinterpret_cast<uint32_t*>(&t);
}
__device__ __forceinline__ float2 unpackbf(uint32_t u) {
    __nv_bfloat162 t = *reinterpret_cast<__nv_bfloat162*>(&u);
    return __bfloat1622float2(t);
}
__device__ __forceinline__ void ldmx4(uint32_t* r, uint32_t addr) {
    asm volatile("ldmatrix.sync.aligned.m8n8.x4.shared.b16 {%0,%1,%2,%3}, [%4];"
        : "=r"(r[0]), "=r"(r[1]), "=r"(r[2]), "=r"(r[3]) : "r"(addr));
}
__device__ __forceinline__ void ldmx4t(uint32_t* r, uint32_t addr) {
    asm volatile("ldmatrix.sync.aligned.m8n8.x4.trans.shared.b16 {%0,%1,%2,%3}, [%4];"
        : "=r"(r[0]), "=r"(r[1]), "=r"(r[2]), "=r"(r[3]) : "r"(addr));
}
__device__ __forceinline__ void mma16816(float* d, const uint32_t* a, const uint32_t* b) {
    asm volatile("mma.sync.aligned.m16n8k16.row.col.f32.bf16.bf16.f32 "
        "{%0,%1,%2,%3}, {%4,%5,%6,%7}, {%8,%9}, {%0,%1,%2,%3};"
        : "+f"(d[0]), "+f"(d[1]), "+f"(d[2]), "+f"(d[3])
        : "r"(a[0]), "r"(a[1]), "r"(a[2]), "r"(a[3]), "r"(b[0]), "r"(b[1]));
}
__device__ __forceinline__ void mma16816b(float* d, const uint32_t* a,
                                          uint32_t b0, uint32_t b1) {
    asm volatile("mma.sync.aligned.m16n8k16.row.col.f32.bf16.bf16.f32 "
        "{%0,%1,%2,%3}, {%4,%5,%6,%7}, {%8,%9}, {%0,%1,%2,%3};"
        : "+f"(d[0]), "+f"(d[1]), "+f"(d[2]), "+f"(d[3])
        : "r"(a[0]), "r"(a[1]), "r"(a[2]), "r"(a[3]), "r"(b0), "r"(b1));
}
__device__ __forceinline__ void cp16(const void* smem_dst, const void* gsrc) {
    uint32_t d = cvta_smem(smem_dst);
    asm volatile("cp.async.cg.shared.global [%0], [%1], 16;" :: "r"(d), "l"(gsrc));
}
#define CP_COMMIT()  asm volatile("cp.async.commit_group;" ::: "memory")
#define CP_WAIT0()   asm volatile("cp.async.wait_group 0;" ::: "memory")
__device__ __forceinline__ float gelu_exact(float v) {
    return 0.5f * v * (1.0f + erff(v * 0.7071067811865476f));
}

// ---------------------------------------------------------------------------
// Single prep kernel: 4 weight casts + bf16 bias table
// ---------------------------------------------------------------------------
__global__ void prep_all(const float* __restrict__ qkv_w, const float* __restrict__ proj_w,
                         const float* __restrict__ mlp_w1, const float* __restrict__ mlp_w2,
                         const int* __restrict__ rel_idx, const float* __restrict__ rpb,
                         __nv_bfloat16* __restrict__ wt, __nv_bfloat16* __restrict__ btab) {
    int i = blockIdx.x * 256 + threadIdx.x;
    if (i < 49152) { wt[i] = __float2bfloat16(qkv_w[i]); return; }
    i -= 49152;
    if (i < 16384) { wt[49152 + i] = __float2bfloat16(proj_w[i]); return; }
    i -= 16384;
    if (i < 65536) { wt[65536 + i] = __float2bfloat16(mlp_w1[i]); return; }
    i -= 65536;
    if (i < 65536) { wt[131072 + i] = __float2bfloat16(mlp_w2[i]); return; }
    i -= 65536;
    if (i < 4 * 98 * 112) {
        int h = i / 10976, rem = i - h * 10976;
        int row = rem / 112, col = rem - row * 112;
        float v = 0.0f;
        if (col < 98) v = rpb[rel_idx[row * 98 + col] * 4 + h] * 1.4426950408889634f;
        btab[i] = __float2bfloat16(v);
    }
}

// ---------------------------------------------------------------------------
// Fused LN1(gather) + QKV GEMM. 512 threads, 16 warps (4x4, 32x32 tiles).
// ---------------------------------------------------------------------------
#define LQ_AS 0
#define LQ_BS 34816
#define LQ_SB 104448              // 384 floats
#define LQ_SMEM (104448 + 1536)   // 105984

__global__ __launch_bounds__(512, 2)
void ln_qkv(const float* __restrict__ x, const float* __restrict__ g,
            const float* __restrict__ beta, const __nv_bfloat16* __restrict__ W,
            const float* __restrict__ bias, __nv_bfloat16* __restrict__ qkv) {
    extern __shared__ char smc[];
    __nv_bfloat16* As = (__nv_bfloat16*)(smc + LQ_AS);
    __nv_bfloat16* Bs = (__nv_bfloat16*)(smc + LQ_BS);
    float*         sb = (float*)(smc + LQ_SB);

    int tid = threadIdx.x, lane = tid & 31, wid = tid >> 5;
    int wm = wid & 3, wn = wid >> 2;
    int m0 = blockIdx.x * 128;

    #pragma unroll
    for (int it = 0; it < 4; it++) {
        int idx = it * 512 + tid;
        int row = idx >> 4, seg = idx & 15;
        cp16(Bs + row * 136 + seg * 8, W + row * 384 + seg * 8);
    }
    CP_COMMIT();
    if (tid < 384) sb[tid] = bias[tid];

    #pragma unroll
    for (int i = 0; i < 8; i++) {
        int r = i * 16 + wid;
        int src = win_row_to_token(m0 + r);
        float4 v = *(const float4*)(x + (size_t)src * 128 + lane * 4);
        float s  = v.x + v.y + v.z + v.w;
        float s2 = fmaf(v.x, v.x, fmaf(v.y, v.y, fmaf(v.z, v.z, v.w * v.w)));
        #pragma unroll
        for (int o = 16; o; o >>= 1) {
            s  += __shfl_xor_sync(0xffffffffu, s,  o);
            s2 += __shfl_xor_sync(0xffffffffu, s2, o);
        }
        float mu  = s * (1.0f / 128.0f);
        float var = s2 * (1.0f / 128.0f) - mu * mu;
        float inv = rsqrtf(var + 1e-5f);
        float4 gv = *(const float4*)(g + lane * 4);
        float4 bv = *(const float4*)(beta + lane * 4);
        uint2 u;
        u.x = packbf((v.x - mu) * inv * gv.x + bv.x, (v.y - mu) * inv * gv.y + bv.y);
        u.y = packbf((v.z - mu) * inv * gv.z + bv.z, (v.w - mu) * inv * gv.w + bv.w);
        *(uint2*)(As + r * 136 + lane * 4) = u;
    }

    uint32_t aAddr  = cvta_smem(As + (wm * 32 + (lane & 15)) * 136 + (lane >> 4) * 8);
    uint32_t bAddr0 = cvta_smem(Bs + (lane & 15) * 136 + wn * 32 + (lane >> 4) * 8);
    int gcol = lane >> 2, t4 = lane & 3;

    for (int c = 0; c < 3; c++) {
        CP_WAIT0();
        __syncthreads();
        if (c < 2) {
            __nv_bfloat16* dst = Bs + ((c + 1) & 1) * 17408;
            const __nv_bfloat16* src = W + (c + 1) * 128;
            #pragma unroll
            for (int it = 0; it < 4; it++) {
                int idx = it * 512 + tid;
                int row = idx >> 4, seg = idx & 15;
                cp16(dst + row * 136 + seg * 8, src + row * 384 + seg * 8);
            }
            CP_COMMIT();
        }

        float acc[2][4][4];
        #pragma unroll
        for (int mi = 0; mi < 2; mi++)
            #pragma unroll
            for (int ni = 0; ni < 4; ni++)
                #pragma unroll
                for (int q = 0; q < 4; q++) acc[mi][ni][q] = 0.0f;

        uint32_t bAddr = bAddr0 + (c & 1) * 34816u;
        #pragma unroll
        for (int s = 0; s < 8; s++) {
            uint32_t aF[2][4];
            #pragma unroll
            for (int mi = 0; mi < 2; mi++)
                ldmx4(aF[mi], aAddr + mi * 4352u + s * 32u);
            uint32_t bF[4][2];
            #pragma unroll
            for (int nq = 0; nq < 2; nq++) {
                uint32_t r[4];
                ldmx4t(r, bAddr + s * 4352u + nq * 32u);
                bF[2 * nq    ][0] = r[0]; bF[2 * nq    ][1] = r[1];
                bF[2 * nq + 1][0] = r[2]; bF[2 * nq + 1][1] = r[3];
            }
            #pragma unroll
            for (int mi = 0; mi < 2; mi++)
                #pragma unroll
                for (int ni = 0; ni < 4; ni++)
                    mma16816(acc[mi][ni], aF[mi], bF[ni]);
        }

        #pragma unroll
        for (int mi = 0; mi < 2; mi++) {
            int rl = wm * 32 + mi * 16 + gcol;
            #pragma unroll
            for (int ni = 0; ni < 4; ni++) {
                int cl = wn * 32 + ni * 8 + t4 * 2;
                float b0 = sb[c * 128 + cl], b1 = sb[c * 128 + cl + 1];
                *(uint32_t*)(qkv + (size_t)(m0 + rl) * 384 + c * 128 + cl) =
                    packbf(acc[mi][ni][0] + b0, acc[mi][ni][1] + b1);
                *(uint32_t*)(qkv + (size_t)(m0 + rl + 8) * 384 + c * 128 + cl) =
                    packbf(acc[mi][ni][2] + b0, acc[mi][ni][3] + b1);
            }
        }
        __syncthreads();
    }
}

// ---------------------------------------------------------------------------
// HMMA attention: one block per (window, head), 256 threads; bf16 bias table.
// ---------------------------------------------------------------------------
#define ASMEM 30720

__global__ __launch_bounds__(256)
void attn_hmma(const __nv_bfloat16* __restrict__ qkv, const __nv_bfloat16* __restrict__ btab,
               __nv_bfloat16* __restrict__ ao) {
    extern __shared__ char smc[];
    __nv_bfloat16* Qs = (__nv_bfloat16*)(smc);
    __nv_bfloat16* Ks = (__nv_bfloat16*)(smc + 10240);
    __nv_bfloat16* Vs = (__nv_bfloat16*)(smc + 20480);

    int tid = threadIdx.x, warp = tid >> 5, lane = tid & 31;
    int g = lane >> 2, t4 = lane & 3;
    int win = blockIdx.x >> 2, head = blockIdx.x & 3;
    const float CEXP = 0.17677669529663687f * 1.4426950408889634f;
    const __nv_bfloat16* bt = btab + head * 10976;

    #pragma unroll
    for (int it = 0; it < 2; it++) {
        int idx = it * 256 + tid;
        int row = idx >> 2, seg = idx & 3;
        uint4 zq = make_uint4(0, 0, 0, 0), zk = zq, zv = zq;
        if (row < 98) {
            const __nv_bfloat16* base = qkv + (size_t)(win * 98 + row) * 384 + head * 32 + seg * 8;
            zq = *(const uint4*)(base);
            zk = *(const uint4*)(base + 128);
            zv = *(const uint4*)(base + 256);
        }
        *(uint4*)(Qs + row * 40 + seg * 8) = zq;
        *(uint4*)(Ks + row * 40 + seg * 8) = zk;
        *(uint4*)(Vs + row * 40 + seg * 8) = zv;
    }
    __syncthreads();

    uint32_t qAddr = cvta_smem(Qs + (warp * 16 + (lane & 15)) * 40 + (lane >> 4) * 8);
    uint32_t kAddr = cvta_smem(Ks + (lane & 15) * 40 + (lane >> 4) * 8);
    uint32_t vAddr = cvta_smem(Vs + (lane & 15) * 40 + (lane >> 4) * 8);

    float sacc[13][4];
    #pragma unroll
    for (int j = 0; j < 13; j++)
        #pragma unroll
        for (int q = 0; q < 4; q++) sacc[j][q] = 0.0f;

    #pragma unroll
    for (int ks = 0; ks < 32; ks += 16) {
        uint32_t aF[4];
        ldmx4(aF, qAddr + ks * 2u);
        #pragma unroll
        for (int j2 = 0; j2 < 7; j2++) {
            uint32_t r[4];
            ldmx4(r, kAddr + j2 * 1280u + ks * 2u);
            mma16816b(sacc[2 * j2], aF, r[0], r[2]);
            if (j2 < 6) mma16816b(sacc[2 * j2 + 1], aF, r[1], r[3]);
        }
    }

    int ra = warp * 16 + g, rb = ra + 8;
    bool oka = ra < 98, okb = rb < 98;
    float rsum0 = 0.0f, rsum1 = 0.0f;
    #pragma unroll
    for (int j = 0; j < 13; j++) {
        int c0 = 8 * j + 2 * t4;
        bool cv = c0 < 98;
        float e0 = 0.0f, e1 = 0.0f, e2 = 0.0f, e3 = 0.0f;
        if (cv && oka) {
            float2 bb = unpackbf(*(const uint32_t*)(bt + ra * 112 + c0));
            e0 = exp2f(fmaf(sacc[j][0], CEXP, bb.x));
            e1 = exp2f(fmaf(sacc[j][1], CEXP, bb.y));
        }
        if (cv && okb) {
            float2 bb = unpackbf(*(const uint32_t*)(bt + rb * 112 + c0));
            e2 = exp2f(fmaf(sacc[j][2], CEXP, bb.x));
            e3 = exp2f(fmaf(sacc[j][3], CEXP, bb.y));
        }
        sacc[j][0] = e0; sacc[j][1] = e1; sacc[j][2] = e2; sacc[j][3] = e3;
        rsum0 += e0 + e1;
        rsum1 += e2 + e3;
    }
    rsum0 += __shfl_xor_sync(0xffffffffu, rsum0, 1);
    rsum0 += __shfl_xor_sync(0xffffffffu, rsum0, 2);
    rsum1 += __shfl_xor_sync(0xffffffffu, rsum1, 1);
    rsum1 += __shfl_xor_sync(0xffffffffu, rsum1, 2);
    float inv0 = 1.0f / rsum0, inv1 = 1.0f / rsum1;

    float oacc[4][4];
    #pragma unroll
    for (int j = 0; j < 4; j++)
        #pragma unroll
        for (int q = 0; q < 4; q++) oacc[j][q] = 0.0f;

    #pragma unroll
    for (int ks2 = 0; ks2 < 7; ks2++) {
        uint32_t bV[4][2];
        #pragma unroll
        for (int nq = 0; nq < 2; nq++) {
            uint32_t r[4];
            ldmx4t(r, vAddr + ks2 * 1280u + nq * 32u);
            bV[2 * nq    ][0] = r[0]; bV[2 * nq    ][1] = r[1];
            bV[2 * nq + 1][0] = r[2]; bV[2 * nq + 1][1] = r[3];
        }
        uint32_t a[4];
        a[0] = packbf(sacc[2 * ks2][0], sacc[2 * ks2][1]);
        a[1] = packbf(sacc[2 * ks2][2], sacc[2 * ks2][3]);
        if (ks2 < 6) {
            a[2] = packbf(sacc[2 * ks2 + 1][0], sacc[2 * ks2 + 1][1]);
            a[3] = packbf(sacc[2 * ks2 + 1][2], sacc[2 * ks2 + 1][3]);
        } else { a[2] = 0u; a[3] = 0u; }
        #pragma unroll
        for (int j = 0; j < 4; j++)
            mma16816(oacc[j], a, bV[j]);
    }

    #pragma unroll
    for (int j = 0; j < 4; j++) {
        int c = head * 32 + 8 * j + 2 * t4;
        if (oka)
            *(uint32_t*)(ao + (size_t)(win * 98 + ra) * 128 + c) =
                packbf(oacc[j][0] * inv0, oacc[j][1] * inv0);
        if (okb)
            *(uint32_t*)(ao + (size_t)(win * 98 + rb) * 128 + c) =
                packbf(oacc[j][2] * inv1, oacc[j][3] * inv1);
    }
}

// ---------------------------------------------------------------------------
// Proj GEMM + residual (scatter). 256 threads, M-tile 64, 4 blocks/SM.
// ---------------------------------------------------------------------------
#define PJ_SMEM 52224   // As[64][136] + Bs[128][136] bf16

__global__ __launch_bounds__(256, 4)
void gemm_proj(const __nv_bfloat16* __restrict__ A, const __nv_bfloat16* __restrict__ W,
               const float* __restrict__ bias, const float* __restrict__ res,
               float* __restrict__ Cout) {
    extern __shared__ char smc[];
    __nv_bfloat16* As = (__nv_bfloat16*)(smc);
    __nv_bfloat16* Bs = (__nv_bfloat16*)(smc + 17408);
    __shared__ int   rowmap[64];
    __shared__ float sbias[128];

    int tid = threadIdx.x, lane = tid & 31, wid = tid >> 5;
    int wm = wid & 1, wn = wid >> 1;
    int m0 = blockIdx.x * 64;

    #pragma unroll
    for (int it = 0; it < 4; it++) {
        int idx = it * 256 + tid;
        int row = idx >> 4, seg = idx & 15;
        cp16(As + row * 136 + seg * 8, A + (size_t)(m0 + row) * 128 + seg * 8);
    }
    #pragma unroll
    for (int it = 0; it < 8; it++) {
        int idx = it * 256 + tid;
        int row = idx >> 4, seg = idx & 15;
        cp16(Bs + row * 136 + seg * 8, W + (size_t)row * 128 + seg * 8);
    }
    CP_COMMIT();
    if (tid < 128) sbias[tid] = bias[tid];
    if (tid < 64)  rowmap[tid] = win_row_to_token(m0 + tid);

    float acc[2][4][4];
    #pragma unroll
    for (int mi = 0; mi < 2; mi++)
        #pragma unroll
        for (int ni = 0; ni < 4; ni++)
            #pragma unroll
            for (int q = 0; q < 4; q++) acc[mi][ni][q] = 0.0f;

    uint32_t aAddr = cvta_smem(As + (wm * 32 + (lane & 15)) * 136 + (lane >> 4) * 8);
    uint32_t bAddr = cvta_smem(Bs + (lane & 15) * 136 + wn * 32 + (lane >> 4) * 8);

    CP_WAIT0();
    __syncthreads();

    #pragma unroll
    for (int s = 0; s < 8; s++) {
        uint32_t aF[2][4];
        #pragma unroll
        for (int mi = 0; mi < 2; mi++)
            ldmx4(aF[mi], aAddr + mi * 4352u + s * 32u);
        uint32_t bF[4][2];
        #pragma unroll
        for (int nq = 0; nq < 2; nq++) {
            uint32_t r[4];
            ldmx4t(r, bAddr + s * 4352u + nq * 32u);
            bF[2 * nq    ][0] = r[0]; bF[2 * nq    ][1] = r[1];
            bF[2 * nq + 1][0] = r[2]; bF[2 * nq + 1][1] = r[3];
        }
        #pragma unroll
        for (int mi = 0; mi < 2; mi++)
            #pragma unroll
            for (int ni = 0; ni < 4; ni++)
                mma16816(acc[mi][ni], aF[mi], bF[ni]);
    }

    int gcol = lane >> 2, t4 = lane & 3;
    #pragma unroll
    for (int mi = 0; mi < 2; mi++) {
        int rl = wm * 32 + mi * 16 + gcol;
        int r0 = rowmap[rl], r1 = rowmap[rl + 8];
        #pragma unroll
        for (int ni = 0; ni < 4; ni++) {
            int cl = wn * 32 + ni * 8 + t4 * 2;
            float b0 = sbias[cl], b1 = sbias[cl + 1];
            size_t o0 = (size_t)r0 * 128 + cl;
            size_t o1 = (size_t)r1 * 128 + cl;
            float2 q0 = *(const float2*)(res + o0);
            float2 q1 = *(const float2*)(res + o1);
            *(float2*)(Cout + o0) = make_float2(acc[mi][ni][0] + b0 + q0.x,
                                                acc[mi][ni][1] + b1 + q0.y);
            *(float2*)(Cout + o1) = make_float2(acc[mi][ni][2] + b0 + q1.x,
                                                acc[mi][ni][3] + b1 + q1.y);
        }
    }
}

// ---------------------------------------------------------------------------
// Fused LN2 + MLP1 + GELU + MLP2 + residual. 1024 threads, 32 warps (4x8),
// warp tile 32x16, double-buffered weights.
// ---------------------------------------------------------------------------
#define FM_AS 0
#define FM_HS 34816
#define FM_W1 69632                  // 2 x 34816
#define FM_W2 139264                 // 2 x 34816
#define FM_B1 208896                 // 512 floats
#define FM_B2 210944                 // 128 floats
#define FM_SMEM 211456

__global__ __launch_bounds__(1024, 1)
void fused_mlp(const float* __restrict__ y2, const float* __restrict__ g,
               const float* __restrict__ beta, const __nv_bfloat16* __restrict__ W1,
               const float* __restrict__ b1, const __nv_bfloat16* __restrict__ W2,
               const float* __restrict__ b2, float* __restrict__ out) {
    extern __shared__ char smc[];
    __nv_bfloat16* As  = (__nv_bfloat16*)(smc + FM_AS);
    __nv_bfloat16* Hs  = (__nv_bfloat16*)(smc + FM_HS);
    __nv_bfloat16* W1s = (__nv_bfloat16*)(smc + FM_W1);
    __nv_bfloat16* W2s = (__nv_bfloat16*)(smc + FM_W2);
    float* sb1 = (float*)(smc + FM_B1);
    float* sb2 = (float*)(smc + FM_B2);

    int tid = threadIdx.x, lane = tid & 31, wid = tid >> 5;
    int wm = wid & 3, wn = wid >> 2;          // 4 m-tiles x 8 n-tiles (32x16)
    int m0 = blockIdx.x * 128;

    // prefetch chunk 0 of W1, W2
    #pragma unroll
    for (int it = 0; it < 2; it++) {
        int idx = it * 1024 + tid;
        int row = idx >> 4, seg = idx & 15;
        cp16(W1s + row * 136 + seg * 8, W1 + row * 512 + seg * 8);
        cp16(W2s + row * 136 + seg * 8, W2 + row * 128 + seg * 8);
    }
    CP_COMMIT();
    if (tid < 512) sb1[tid] = b1[tid];
    if (tid < 128) sb2[tid] = b2[tid];

    // LN2 -> As
    #pragma unroll
    for (int i = 0; i < 4; i++) {
        int r = i * 32 + wid;
        float4 v = *(const float4*)(y2 + (size_t)(m0 + r) * 128 + lane * 4);
        float s  = v.x + v.y + v.z + v.w;
        float s2 = fmaf(v.x, v.x, fmaf(v.y, v.y, fmaf(v.z, v.z, v.w * v.w)));
        #pragma unroll
        for (int o = 16; o; o >>= 1) {
            s  += __shfl_xor_sync(0xffffffffu, s,  o);
            s2 += __shfl_xor_sync(0xffffffffu, s2, o);
        }
        float mu  = s * (1.0f / 128.0f);
        float var = s2 * (1.0f / 128.0f) - mu * mu;
        float inv = rsqrtf(var + 1e-5f);
        float4 gv = *(const float4*)(g + lane * 4);
        float4 bv = *(const float4*)(beta + lane * 4);
        uint2 u;
        u.x = packbf((v.x - mu) * inv * gv.x + bv.x, (v.y - mu) * inv * gv.y + bv.y);
        u.y = packbf((v.z - mu) * inv * gv.z + bv.z, (v.w - mu) * inv * gv.w + bv.w);
        *(uint2*)(As + r * 136 + lane * 4) = u;
    }

    uint32_t aAddr   = cvta_smem(As + (wm * 32 + (lane & 15)) * 136 + (lane >> 4) * 8);
    uint32_t hAddrW  = cvta_smem(Hs + (wm * 32 + (lane & 15)) * 136 + (lane >> 4) * 8);
    uint32_t w1Addr0 = cvta_smem(W1s + (lane & 15) * 136 + wn * 16 + (lane >> 4) * 8);
    uint32_t w2Addr0 = cvta_smem(W2s + (lane & 15) * 136 + wn * 16 + (lane >> 4) * 8);
    int gcol = lane >> 2, t4 = lane & 3;

    float oacc[2][2][4];
    #pragma unroll
    for (int mi = 0; mi < 2; mi++)
        #pragma unroll
        for (int ni = 0; ni < 2; ni++)
            #pragma unroll
            for (int q = 0; q < 4; q++) oacc[mi][ni][q] = 0.0f;

    for (int c = 0; c < 4; c++) {
        CP_WAIT0();
        __syncthreads();
        if (c < 3) {
            __nv_bfloat16* d1 = W1s + ((c + 1) & 1) * 17408;
            __nv_bfloat16* d2 = W2s + ((c + 1) & 1) * 17408;
            const __nv_bfloat16* s1 = W1 + (c + 1) * 128;
            const __nv_bfloat16* s2 = W2 + (size_t)(c + 1) * 128 * 128;
            #pragma unroll
            for (int it = 0; it < 2; it++) {
                int idx = it * 1024 + tid;
                int row = idx >> 4, seg = idx & 15;
                cp16(d1 + row * 136 + seg * 8, s1 + row * 512 + seg * 8);
                cp16(d2 + row * 136 + seg * 8, s2 + row * 128 + seg * 8);
            }
            CP_COMMIT();
        }

        // H = A @ W1c
        float hacc[2][2][4];
        #pragma unroll
        for (int mi = 0; mi < 2; mi++)
            #pragma unroll
            for (int ni = 0; ni < 2; ni++)
                #pragma unroll
                for (int q = 0; q < 4; q++) hacc[mi][ni][q] = 0.0f;

        uint32_t w1Addr = w1Addr0 + (c & 1) * 34816u;
        #pragma unroll
        for (int s = 0; s < 8; s++) {
            uint32_t aF[2][4];
            #pragma unroll
            for (int mi = 0; mi < 2; mi++)
                ldmx4(aF[mi], aAddr + mi * 4352u + s * 32u);
            uint32_t r[4];
            ldmx4t(r, w1Addr + s * 4352u);
            #pragma unroll
            for (int mi = 0; mi < 2; mi++) {
                mma16816b(hacc[mi][0], aF[mi], r[0], r[1]);
                mma16816b(hacc[mi][1], aF[mi], r[2], r[3]);
            }
        }

        // gelu + pack -> Hs
        #pragma unroll
        for (int mi = 0; mi < 2; mi++) {
            int rl = wm * 32 + mi * 16 + gcol;
            #pragma unroll
            for (int ni = 0; ni < 2; ni++) {
                int cl = wn * 16 + ni * 8 + t4 * 2;
                float b0 = sb1[c * 128 + cl], b1v = sb1[c * 128 + cl + 1];
                *(uint32_t*)(Hs + rl * 136 + cl) =
                    packbf(gelu_exact(hacc[mi][ni][0] + b0), gelu_exact(hacc[mi][ni][1] + b1v));
                *(uint32_t*)(Hs + (rl + 8) * 136 + cl) =
                    packbf(gelu_exact(hacc[mi][ni][2] + b0), gelu_exact(hacc[mi][ni][3] + b1v));
            }
        }
        __syncthreads();

        // oacc += H @ W2c
        uint32_t w2Addr = w2Addr0 + (c & 1) * 34816u;
        #pragma unroll
        for (int s = 0; s < 8; s++) {
            uint32_t aF[2][4];
            #pragma unroll
            for (int mi = 0; mi < 2; mi++)
                ldmx4(aF[mi], hAddrW + mi * 4352u + s * 32u);
            uint32_t r[4];
            ldmx4t(r, w2Addr + s * 4352u);
            #pragma unroll
            for (int mi = 0; mi < 2; mi++) {
                mma16816b(oacc[mi][0], aF[mi], r[0], r[1]);
                mma16816b(oacc[mi][1], aF[mi], r[2], r[3]);
            }
        }
    }

    // epilogue: +b2 + residual y2 -> out fp32
    #pragma unroll
    for (int mi = 0; mi < 2; mi++) {
        int rl = wm * 32 + mi * 16 + gcol;
        #pragma unroll
        for (int ni = 0; ni < 2; ni++) {
            int cl = wn * 16 + ni * 8 + t4 * 2;
            float b0 = sb2[cl], b1v = sb2[cl + 1];
            size_t o0 = (size_t)(m0 + rl) * 128 + cl;
            size_t o1 = (size_t)(m0 + rl + 8) * 128 + cl;
            float2 q0 = *(const float2*)(y2 + o0);
            float2 q1 = *(const float2*)(y2 + o1);
            *(float2*)(out + o0) = make_float2(oacc[mi][ni][0] + b0 + q0.x,
                                               oacc[mi][ni][1] + b1v + q0.y);
            *(float2*)(out + o1) = make_float2(oacc[mi][ni][2] + b0 + q1.x,
                                               oacc[mi][ni][3] + b1v + q1.y);
        }
    }
}

// ---------------------------------------------------------------------------
extern "C" void kernel_launch(void* const* d_in, const int* in_sizes, int n_in,
                              void* d_out, int out_size) {
    (void)in_sizes; (void)n_in; (void)out_size;
    const float* x       = (const float*)d_in[0];
    const int*   rel_idx = (const int*)  d_in[1];
    const float* rpb     = (const float*)d_in[2];
    const float* qkv_w   = (const float*)d_in[3];
    const float* qkv_b   = (const float*)d_in[4];
    const float* proj_w  = (const float*)d_in[5];
    const float* proj_b  = (const float*)d_in[6];
    const float* ln1_g   = (const float*)d_in[7];
    const float* ln1_b   = (const float*)d_in[8];
    const float* ln2_g   = (const float*)d_in[9];
    const float* ln2_b   = (const float*)d_in[10];
    const float* mlp_w1  = (const float*)d_in[11];
    const float* mlp_b1  = (const float*)d_in[12];
    const float* mlp_w2  = (const float*)d_in[13];
    const float* mlp_b2  = (const float*)d_in[14];
    float* out = (float*)d_out;

    __nv_bfloat16 *qkvb, *ao, *wt, *btab;
    float *y2;
    cudaGetSymbolAddress((void**)&qkvb, g_qkv);
    cudaGetSymbolAddress((void**)&ao,   g_ao);
    cudaGetSymbolAddress((void**)&y2,   g_y2);
    cudaGetSymbolAddress((void**)&wt,   g_wt);
    cudaGetSymbolAddress((void**)&btab, g_btab);
    __nv_bfloat16* wt_qkv = wt;             // [128][384]
    __nv_bfloat16* wt_prj = wt + 49152;     // [128][128]
    __nv_bfloat16* wt_m1  = wt + 65536;     // [128][512]
    __nv_bfloat16* wt_m2  = wt + 131072;    // [512][128]

    cudaFuncSetAttribute(ln_qkv,    cudaFuncAttributeMaxDynamicSharedMemorySize, LQ_SMEM);
    cudaFuncSetAttribute(attn_hmma, cudaFuncAttributeMaxDynamicSharedMemorySize, ASMEM);
    cudaFuncSetAttribute(gemm_proj, cudaFuncAttributeMaxDynamicSharedMemorySize, PJ_SMEM);
    cudaFuncSetAttribute(fused_mlp, cudaFuncAttributeMaxDynamicSharedMemorySize, FM_SMEM);

    prep_all<<<940, 256>>>(qkv_w, proj_w, mlp_w1, mlp_w2, rel_idx, rpb, wt, btab);
    ln_qkv<<<784, 512, LQ_SMEM>>>(x, ln1_g, ln1_b, wt_qkv, qkv_b, qkvb);
    attn_hmma<<<4096, 256, ASMEM>>>(qkvb, btab, ao);
    gemm_proj<<<1568, 256, PJ_SMEM>>>(ao, wt_prj, proj_b, x, y2);
    fused_mlp<<<784, 1024, FM_SMEM>>>(y2, ln2_g, ln2_b, wt_m1, mlp_b1, wt_m2, mlp_b2, out);
}

// round 9
// speedup vs baseline: 1.1300x; 1.1300x over previous
#include <cuda_runtime.h>
#include <cuda_bf16.h>
#include <math.h>
#include <stdint.h>

// ---------------------------------------------------------------------------
// SwinTransformerBlock3D  (B=4, D=8, H=56, W=56, C=128, WIN=(2,7,7), HEADS=4)
// ---------------------------------------------------------------------------

#define M_TOK 100352            // 4*8*56*56 == 1024 windows * 98 tokens

__device__ __nv_bfloat16 g_qkv[(size_t)M_TOK*384];   // qkv, window order
__device__ __nv_bfloat16 g_ao [(size_t)M_TOK*128];   // attn out, window order
__device__ float         g_y2 [(size_t)M_TOK*128];   // x + proj (spatial)
__device__ __nv_bfloat16 g_wt [196608];              // bf16 weights
__device__ float         g_btab[4*98*112];           // log2e * rpb[rel_idx], padded

// window row r -> spatial token (roll -SHIFT folded in); self-inverse mapping.
__device__ __forceinline__ int win_row_to_token(int r) {
    int win = r / 98;
    int n   = r - win * 98;
    int ww = win & 7;
    int wh = (win >> 3) & 7;
    int wd = (win >> 6) & 3;
    int b  = win >> 8;
    int id  = n / 49;
    int rem = n - id * 49;
    int ih  = rem / 7;
    int iw  = rem - ih * 7;
    int d = wd * 2 + id;
    int h = wh * 7 + ih;
    int w = ww * 7 + iw;
    int ds = d + 1;  if (ds >= 8)  ds -= 8;
    int hs = h + 3;  if (hs >= 56) hs -= 56;
    int ws = w + 3;  if (ws >= 56) ws -= 56;
    return ((b * 8 + ds) * 56 + hs) * 56 + ws;
}

// ---------------------------------------------------------------------------
// helpers
// ---------------------------------------------------------------------------
__device__ __forceinline__ uint32_t cvta_smem(const void* p) {
    uint32_t a;
    asm("{ .reg .u64 t; cvta.to.shared.u64 t, %1; cvt.u32.u64 %0, t; }"
        : "=r"(a) : "l"(p));
    return a;
}
__device__ __forceinline__ uint32_t packbf(float a, float b) {
    __nv_bfloat162 t = __floats2bfloat162_rn(a, b);
    return *reinterpret_cast<uint32_t*>(&t);
}
__device__ __forceinline__ void ldmx4(uint32_t* r, uint32_t addr) {
    asm volatile("ldmatrix.sync.aligned.m8n8.x4.shared.b16 {%0,%1,%2,%3}, [%4];"
        : "=r"(r[0]), "=r"(r[1]), "=r"(r[2]), "=r"(r[3]) : "r"(addr));
}
__device__ __forceinline__ void ldmx4t(uint32_t* r, uint32_t addr) {
    asm volatile("ldmatrix.sync.aligned.m8n8.x4.trans.shared.b16 {%0,%1,%2,%3}, [%4];"
        : "=r"(r[0]), "=r"(r[1]), "=r"(r[2]), "=r"(r[3]) : "r"(addr));
}
__device__ __forceinline__ void mma16816(float* d, const uint32_t* a, const uint32_t* b) {
    asm volatile("mma.sync.aligned.m16n8k16.row.col.f32.bf16.bf16.f32 "
        "{%0,%1,%2,%3}, {%4,%5,%6,%7}, {%8,%9}, {%0,%1,%2,%3};"
        : "+f"(d[0]), "+f"(d[1]), "+f"(d[2]), "+f"(d[3])
        : "r"(a[0]), "r"(a[1]), "r"(a[2]), "r"(a[3]), "r"(b[0]), "r"(b[1]));
}
__device__ __forceinline__ void mma16816b(float* d, const uint32_t* a,
                                          uint32_t b0, uint32_t b1) {
    asm volatile("mma.sync.aligned.m16n8k16.row.col.f32.bf16.bf16.f32 "
        "{%0,%1,%2,%3}, {%4,%5,%6,%7}, {%8,%9}, {%0,%1,%2,%3};"
        : "+f"(d[0]), "+f"(d[1]), "+f"(d[2]), "+f"(d[3])
        : "r"(a[0]), "r"(a[1]), "r"(a[2]), "r"(a[3]), "r"(b0), "r"(b1));
}
__device__ __forceinline__ void cp16(const void* smem_dst, const void* gsrc) {
    uint32_t d = cvta_smem(smem_dst);
    asm volatile("cp.async.cg.shared.global [%0], [%1], 16;" :: "r"(d), "l"(gsrc));
}
#define CP_COMMIT()  asm volatile("cp.async.commit_group;" ::: "memory")
#define CP_WAIT1()   asm volatile("cp.async.wait_group 1;" ::: "memory")
#define CP_WAIT0()   asm volatile("cp.async.wait_group 0;" ::: "memory")
__device__ __forceinline__ float gelu_exact(float v) {
    return 0.5f * v * (1.0f + erff(v * 0.7071067811865476f));
}

// ---------------------------------------------------------------------------
// Single prep kernel: 4 weight casts + bias table
// ---------------------------------------------------------------------------
__global__ void prep_all(const float* __restrict__ qkv_w, const float* __restrict__ proj_w,
                         const float* __restrict__ mlp_w1, const float* __restrict__ mlp_w2,
                         const int* __restrict__ rel_idx, const float* __restrict__ rpb,
                         __nv_bfloat16* __restrict__ wt, float* __restrict__ btab) {
    int i = blockIdx.x * 256 + threadIdx.x;
    if (i < 49152) { wt[i] = __float2bfloat16(qkv_w[i]); return; }
    i -= 49152;
    if (i < 16384) { wt[49152 + i] = __float2bfloat16(proj_w[i]); return; }
    i -= 16384;
    if (i < 65536) { wt[65536 + i] = __float2bfloat16(mlp_w1[i]); return; }
    i -= 65536;
    if (i < 65536) { wt[131072 + i] = __float2bfloat16(mlp_w2[i]); return; }
    i -= 65536;
    if (i < 4 * 98 * 112) {
        int h = i / 10976, rem = i - h * 10976;
        int row = rem / 112, col = rem - row * 112;
        float v = 0.0f;
        if (col < 98) v = rpb[rel_idx[row * 98 + col] * 4 + h] * 1.4426950408889634f;
        btab[i] = v;
    }
}

// ---------------------------------------------------------------------------
// Fused LN1(gather) + QKV GEMM. 512 threads, 16 warps (4x4, 32x32 tiles).
// ---------------------------------------------------------------------------
#define LQ_AS 0
#define LQ_BS 34816
#define LQ_SB 104448              // 384 floats
#define LQ_SMEM (104448 + 1536)   // 105984

__global__ __launch_bounds__(512, 2)
void ln_qkv(const float* __restrict__ x, const float* __restrict__ g,
            const float* __restrict__ beta, const __nv_bfloat16* __restrict__ W,
            const float* __restrict__ bias, __nv_bfloat16* __restrict__ qkv) {
    extern __shared__ char smc[];
    __nv_bfloat16* As = (__nv_bfloat16*)(smc + LQ_AS);
    __nv_bfloat16* Bs = (__nv_bfloat16*)(smc + LQ_BS);
    float*         sb = (float*)(smc + LQ_SB);

    int tid = threadIdx.x, lane = tid & 31, wid = tid >> 5;
    int wm = wid & 3, wn = wid >> 2;
    int m0 = blockIdx.x * 128;

    #pragma unroll
    for (int it = 0; it < 4; it++) {
        int idx = it * 512 + tid;
        int row = idx >> 4, seg = idx & 15;
        cp16(Bs + row * 136 + seg * 8, W + row * 384 + seg * 8);
    }
    CP_COMMIT();
    if (tid < 384) sb[tid] = bias[tid];

    #pragma unroll
    for (int i = 0; i < 8; i++) {
        int r = i * 16 + wid;
        int src = win_row_to_token(m0 + r);
        float4 v = *(const float4*)(x + (size_t)src * 128 + lane * 4);
        float s  = v.x + v.y + v.z + v.w;
        float s2 = fmaf(v.x, v.x, fmaf(v.y, v.y, fmaf(v.z, v.z, v.w * v.w)));
        #pragma unroll
        for (int o = 16; o; o >>= 1) {
            s  += __shfl_xor_sync(0xffffffffu, s,  o);
            s2 += __shfl_xor_sync(0xffffffffu, s2, o);
        }
        float mu  = s * (1.0f / 128.0f);
        float var = s2 * (1.0f / 128.0f) - mu * mu;
        float inv = rsqrtf(var + 1e-5f);
        float4 gv = *(const float4*)(g + lane * 4);
        float4 bv = *(const float4*)(beta + lane * 4);
        uint2 u;
        u.x = packbf((v.x - mu) * inv * gv.x + bv.x, (v.y - mu) * inv * gv.y + bv.y);
        u.y = packbf((v.z - mu) * inv * gv.z + bv.z, (v.w - mu) * inv * gv.w + bv.w);
        *(uint2*)(As + r * 136 + lane * 4) = u;
    }

    uint32_t aAddr  = cvta_smem(As + (wm * 32 + (lane & 15)) * 136 + (lane >> 4) * 8);
    uint32_t bAddr0 = cvta_smem(Bs + (lane & 15) * 136 + wn * 32 + (lane >> 4) * 8);
    int gcol = lane >> 2, t4 = lane & 3;

    for (int c = 0; c < 3; c++) {
        CP_WAIT0();
        __syncthreads();
        if (c < 2) {
            __nv_bfloat16* dst = Bs + ((c + 1) & 1) * 17408;
            const __nv_bfloat16* src = W + (c + 1) * 128;
            #pragma unroll
            for (int it = 0; it < 4; it++) {
                int idx = it * 512 + tid;
                int row = idx >> 4, seg = idx & 15;
                cp16(dst + row * 136 + seg * 8, src + row * 384 + seg * 8);
            }
            CP_COMMIT();
        }

        float acc[2][4][4];
        #pragma unroll
        for (int mi = 0; mi < 2; mi++)
            #pragma unroll
            for (int ni = 0; ni < 4; ni++)
                #pragma unroll
                for (int q = 0; q < 4; q++) acc[mi][ni][q] = 0.0f;

        uint32_t bAddr = bAddr0 + (c & 1) * 34816u;
        #pragma unroll
        for (int s = 0; s < 8; s++) {
            uint32_t aF[2][4];
            #pragma unroll
            for (int mi = 0; mi < 2; mi++)
                ldmx4(aF[mi], aAddr + mi * 4352u + s * 32u);
            uint32_t bF[4][2];
            #pragma unroll
            for (int nq = 0; nq < 2; nq++) {
                uint32_t r[4];
                ldmx4t(r, bAddr + s * 4352u + nq * 32u);
                bF[2 * nq    ][0] = r[0]; bF[2 * nq    ][1] = r[1];
                bF[2 * nq + 1][0] = r[2]; bF[2 * nq + 1][1] = r[3];
            }
            #pragma unroll
            for (int mi = 0; mi < 2; mi++)
                #pragma unroll
                for (int ni = 0; ni < 4; ni++)
                    mma16816(acc[mi][ni], aF[mi], bF[ni]);
        }

        #pragma unroll
        for (int mi = 0; mi < 2; mi++) {
            int rl = wm * 32 + mi * 16 + gcol;
            #pragma unroll
            for (int ni = 0; ni < 4; ni++) {
                int cl = wn * 32 + ni * 8 + t4 * 2;
                float b0 = sb[c * 128 + cl], b1 = sb[c * 128 + cl + 1];
                *(uint32_t*)(qkv + (size_t)(m0 + rl) * 384 + c * 128 + cl) =
                    packbf(acc[mi][ni][0] + b0, acc[mi][ni][1] + b1);
                *(uint32_t*)(qkv + (size_t)(m0 + rl + 8) * 384 + c * 128 + cl) =
                    packbf(acc[mi][ni][2] + b0, acc[mi][ni][3] + b1);
            }
        }
        __syncthreads();
    }
}

// ---------------------------------------------------------------------------
// HMMA attention: one block per (window, head), 256 threads (8 warps x 16 rows).
// ---------------------------------------------------------------------------
#define ASMEM 30720

__global__ __launch_bounds__(256)
void attn_hmma(const __nv_bfloat16* __restrict__ qkv, const float* __restrict__ btab,
               __nv_bfloat16* __restrict__ ao) {
    extern __shared__ char smc[];
    __nv_bfloat16* Qs = (__nv_bfloat16*)(smc);
    __nv_bfloat16* Ks = (__nv_bfloat16*)(smc + 10240);
    __nv_bfloat16* Vs = (__nv_bfloat16*)(smc + 20480);

    int tid = threadIdx.x, warp = tid >> 5, lane = tid & 31;
    int g = lane >> 2, t4 = lane & 3;
    int win = blockIdx.x >> 2, head = blockIdx.x & 3;
    const float CEXP = 0.17677669529663687f * 1.4426950408889634f;
    const float* bt = btab + head * 10976;

    #pragma unroll
    for (int it = 0; it < 2; it++) {
        int idx = it * 256 + tid;
        int row = idx >> 2, seg = idx & 3;
        uint4 zq = make_uint4(0, 0, 0, 0), zk = zq, zv = zq;
        if (row < 98) {
            const __nv_bfloat16* base = qkv + (size_t)(win * 98 + row) * 384 + head * 32 + seg * 8;
            zq = *(const uint4*)(base);
            zk = *(const uint4*)(base + 128);
            zv = *(const uint4*)(base + 256);
        }
        *(uint4*)(Qs + row * 40 + seg * 8) = zq;
        *(uint4*)(Ks + row * 40 + seg * 8) = zk;
        *(uint4*)(Vs + row * 40 + seg * 8) = zv;
    }
    __syncthreads();

    uint32_t qAddr = cvta_smem(Qs + (warp * 16 + (lane & 15)) * 40 + (lane >> 4) * 8);
    uint32_t kAddr = cvta_smem(Ks + (lane & 15) * 40 + (lane >> 4) * 8);
    uint32_t vAddr = cvta_smem(Vs + (lane & 15) * 40 + (lane >> 4) * 8);

    float sacc[13][4];
    #pragma unroll
    for (int j = 0; j < 13; j++)
        #pragma unroll
        for (int q = 0; q < 4; q++) sacc[j][q] = 0.0f;

    #pragma unroll
    for (int ks = 0; ks < 32; ks += 16) {
        uint32_t aF[4];
        ldmx4(aF, qAddr + ks * 2u);
        #pragma unroll
        for (int j2 = 0; j2 < 7; j2++) {
            uint32_t r[4];
            ldmx4(r, kAddr + j2 * 1280u + ks * 2u);
            mma16816b(sacc[2 * j2], aF, r[0], r[2]);
            if (j2 < 6) mma16816b(sacc[2 * j2 + 1], aF, r[1], r[3]);
        }
    }

    int ra = warp * 16 + g, rb = ra + 8;
    bool oka = ra < 98, okb = rb < 98;
    float rsum0 = 0.0f, rsum1 = 0.0f;
    #pragma unroll
    for (int j = 0; j < 13; j++) {
        int c0 = 8 * j + 2 * t4;
        bool cv = c0 < 98;
        float e0 = 0.0f, e1 = 0.0f, e2 = 0.0f, e3 = 0.0f;
        if (cv && oka) {
            float2 bb = *(const float2*)(bt + ra * 112 + c0);
            e0 = exp2f(fmaf(sacc[j][0], CEXP, bb.x));
            e1 = exp2f(fmaf(sacc[j][1], CEXP, bb.y));
        }
        if (cv && okb) {
            float2 bb = *(const float2*)(bt + rb * 112 + c0);
            e2 = exp2f(fmaf(sacc[j][2], CEXP, bb.x));
            e3 = exp2f(fmaf(sacc[j][3], CEXP, bb.y));
        }
        sacc[j][0] = e0; sacc[j][1] = e1; sacc[j][2] = e2; sacc[j][3] = e3;
        rsum0 += e0 + e1;
        rsum1 += e2 + e3;
    }
    rsum0 += __shfl_xor_sync(0xffffffffu, rsum0, 1);
    rsum0 += __shfl_xor_sync(0xffffffffu, rsum0, 2);
    rsum1 += __shfl_xor_sync(0xffffffffu, rsum1, 1);
    rsum1 += __shfl_xor_sync(0xffffffffu, rsum1, 2);
    float inv0 = 1.0f / rsum0, inv1 = 1.0f / rsum1;

    float oacc[4][4];
    #pragma unroll
    for (int j = 0; j < 4; j++)
        #pragma unroll
        for (int q = 0; q < 4; q++) oacc[j][q] = 0.0f;

    #pragma unroll
    for (int ks2 = 0; ks2 < 7; ks2++) {
        uint32_t bV[4][2];
        #pragma unroll
        for (int nq = 0; nq < 2; nq++) {
            uint32_t r[4];
            ldmx4t(r, vAddr + ks2 * 1280u + nq * 32u);
            bV[2 * nq    ][0] = r[0]; bV[2 * nq    ][1] = r[1];
            bV[2 * nq + 1][0] = r[2]; bV[2 * nq + 1][1] = r[3];
        }
        uint32_t a[4];
        a[0] = packbf(sacc[2 * ks2][0], sacc[2 * ks2][1]);
        a[1] = packbf(sacc[2 * ks2][2], sacc[2 * ks2][3]);
        if (ks2 < 6) {
            a[2] = packbf(sacc[2 * ks2 + 1][0], sacc[2 * ks2 + 1][1]);
            a[3] = packbf(sacc[2 * ks2 + 1][2], sacc[2 * ks2 + 1][3]);
        } else { a[2] = 0u; a[3] = 0u; }
        #pragma unroll
        for (int j = 0; j < 4; j++)
            mma16816(oacc[j], a, bV[j]);
    }

    #pragma unroll
    for (int j = 0; j < 4; j++) {
        int c = head * 32 + 8 * j + 2 * t4;
        if (oka)
            *(uint32_t*)(ao + (size_t)(win * 98 + ra) * 128 + c) =
                packbf(oacc[j][0] * inv0, oacc[j][1] * inv0);
        if (okb)
            *(uint32_t*)(ao + (size_t)(win * 98 + rb) * 128 + c) =
                packbf(oacc[j][2] * inv1, oacc[j][3] * inv1);
    }
}

// ---------------------------------------------------------------------------
// Proj GEMM + residual (scatter). 256 threads, 2-stage cp.async (best measured).
// ---------------------------------------------------------------------------
__global__ __launch_bounds__(256)
void gemm_proj(const __nv_bfloat16* __restrict__ A, const __nv_bfloat16* __restrict__ W,
               const float* __restrict__ bias, const float* __restrict__ res,
               float* __restrict__ Cout) {
    __shared__ __nv_bfloat16 As[2][128][40];
    __shared__ __nv_bfloat16 Bs[2][32][136];
    __shared__ int   rowmap[128];
    __shared__ float sbias[128];

    const int Nn = 128, K = 128;
    int tid = threadIdx.x, lane = tid & 31, wid = tid >> 5;
    int wm = wid & 3, wn = wid >> 2;
    int m0 = blockIdx.x * 128;

    if (tid < 128) {
        sbias[tid] = bias[tid];
        rowmap[tid] = win_row_to_token(m0 + tid);
    }

    int arow = tid >> 2, aseg = tid & 3;
    int brow = tid >> 4, bseg = tid & 15;

    float acc[2][8][4];
    #pragma unroll
    for (int mi = 0; mi < 2; mi++)
        #pragma unroll
        for (int ni = 0; ni < 8; ni++)
            #pragma unroll
            for (int q = 0; q < 4; q++) acc[mi][ni][q] = 0.0f;

    uint32_t aAddr = cvta_smem(&As[0][wm * 32 + (lane & 15)][(lane >> 4) * 8]);
    uint32_t bAddr = cvta_smem(&Bs[0][(lane & 15)][wn * 64 + (lane >> 4) * 8]);

    #pragma unroll
    for (int i = 0; i < 2; i++)
        cp16(&As[0][arow + i * 64][aseg * 8], A + (size_t)(m0 + arow + i * 64) * K + aseg * 8);
    #pragma unroll
    for (int i = 0; i < 2; i++)
        cp16(&Bs[0][brow + i * 16][bseg * 8], W + (size_t)(brow + i * 16) * Nn + bseg * 8);
    CP_COMMIT();

    const int nk = 4;
    for (int c = 0; c < nk; c++) {
        if (c + 1 < nk) {
            int kc = (c + 1) << 5, s = (c + 1) & 1;
            #pragma unroll
            for (int i = 0; i < 2; i++)
                cp16(&As[s][arow + i * 64][aseg * 8],
                     A + (size_t)(m0 + arow + i * 64) * K + kc + aseg * 8);
            #pragma unroll
            for (int i = 0; i < 2; i++)
                cp16(&Bs[s][brow + i * 16][bseg * 8],
                     W + (size_t)(kc + brow + i * 16) * Nn + bseg * 8);
        }
        CP_COMMIT();
        CP_WAIT1();
        __syncthreads();

        uint32_t aOff = aAddr + (c & 1) * 10240u;
        uint32_t bOff = bAddr + (c & 1) * 8704u;
        #pragma unroll
        for (int ks = 0; ks < 32; ks += 16) {
            uint32_t aF[2][4];
            #pragma unroll
            for (int mi = 0; mi < 2; mi++)
                ldmx4(aF[mi], aOff + (mi * 16) * 80u + ks * 2u);
            uint32_t bF[8][2];
            #pragma unroll
            for (int np = 0; np < 4; np++) {
                uint32_t r[4];
                ldmx4t(r, bOff + ks * 272u + np * 32u);
                bF[2 * np    ][0] = r[0]; bF[2 * np    ][1] = r[1];
                bF[2 * np + 1][0] = r[2]; bF[2 * np + 1][1] = r[3];
            }
            #pragma unroll
            for (int mi = 0; mi < 2; mi++)
                #pragma unroll
                for (int ni = 0; ni < 8; ni++)
                    mma16816(acc[mi][ni], aF[mi], bF[ni]);
        }
        __syncthreads();
    }

    int g = lane >> 2, t4 = lane & 3;
    #pragma unroll
    for (int mi = 0; mi < 2; mi++) {
        int rl = wm * 32 + mi * 16 + g;
        int r0 = rowmap[rl], r1 = rowmap[rl + 8];
        #pragma unroll
        for (int ni = 0; ni < 8; ni++) {
            int cl = wn * 64 + ni * 8 + t4 * 2;
            float b0 = sbias[cl], b1 = sbias[cl + 1];
            size_t o0 = (size_t)r0 * Nn + cl;
            size_t o1 = (size_t)r1 * Nn + cl;
            float2 q0 = *(const float2*)(res + o0);
            float2 q1 = *(const float2*)(res + o1);
            *(float2*)(Cout + o0) = make_float2(acc[mi][ni][0] + b0 + q0.x,
                                                acc[mi][ni][1] + b1 + q0.y);
            *(float2*)(Cout + o1) = make_float2(acc[mi][ni][2] + b0 + q1.x,
                                                acc[mi][ni][3] + b1 + q1.y);
        }
    }
}

// ---------------------------------------------------------------------------
// Fused LN2 + MLP1 + GELU + MLP2 + residual. 256 threads, 8 warps, m-split:
// warp owns 16 rows x full 128 cols. H stays register-resident: the gelu'd
// phase-1 accumulator fragments ARE the phase-2 A-fragments (no Hs, no mid-
// chunk syncs). LN'd A-fragments loaded once, reused across all 4 chunks.
// ---------------------------------------------------------------------------
#define FM_AS 0
#define FM_W1 34816                  // 2 x 34816
#define FM_W2 104448                 // 2 x 34816
#define FM_B1 174080                 // 512 floats
#define FM_B2 176128                 // 128 floats
#define FM_SMEM 176640

__global__ __launch_bounds__(256, 1)
void fused_mlp(const float* __restrict__ y2, const float* __restrict__ g,
               const float* __restrict__ beta, const __nv_bfloat16* __restrict__ W1,
               const float* __restrict__ b1, const __nv_bfloat16* __restrict__ W2,
               const float* __restrict__ b2, float* __restrict__ out) {
    extern __shared__ char smc[];
    __nv_bfloat16* As  = (__nv_bfloat16*)(smc + FM_AS);
    __nv_bfloat16* W1s = (__nv_bfloat16*)(smc + FM_W1);
    __nv_bfloat16* W2s = (__nv_bfloat16*)(smc + FM_W2);
    float* sb1 = (float*)(smc + FM_B1);
    float* sb2 = (float*)(smc + FM_B2);

    int tid = threadIdx.x, lane = tid & 31, wid = tid >> 5;
    int m0 = blockIdx.x * 128;

    // prefetch chunk 0 of W1 (cols 0..127) and W2 (rows 0..127)
    #pragma unroll
    for (int it = 0; it < 8; it++) {
        int idx = it * 256 + tid;
        int row = idx >> 4, seg = idx & 15;
        cp16(W1s + row * 136 + seg * 8, W1 + row * 512 + seg * 8);
        cp16(W2s + row * 136 + seg * 8, W2 + (size_t)row * 128 + seg * 8);
    }
    CP_COMMIT();
    sb1[tid] = b1[tid];
    sb1[256 + tid] = b1[256 + tid];
    if (tid < 128) sb2[tid] = b2[tid];

    // LN2 -> As
    #pragma unroll
    for (int i = 0; i < 16; i++) {
        int r = i * 8 + wid;
        float4 v = *(const float4*)(y2 + (size_t)(m0 + r) * 128 + lane * 4);
        float s  = v.x + v.y + v.z + v.w;
        float s2 = fmaf(v.x, v.x, fmaf(v.y, v.y, fmaf(v.z, v.z, v.w * v.w)));
        #pragma unroll
        for (int o = 16; o; o >>= 1) {
            s  += __shfl_xor_sync(0xffffffffu, s,  o);
            s2 += __shfl_xor_sync(0xffffffffu, s2, o);
        }
        float mu  = s * (1.0f / 128.0f);
        float var = s2 * (1.0f / 128.0f) - mu * mu;
        float inv = rsqrtf(var + 1e-5f);
        float4 gv = *(const float4*)(g + lane * 4);
        float4 bv = *(const float4*)(beta + lane * 4);
        uint2 u;
        u.x = packbf((v.x - mu) * inv * gv.x + bv.x, (v.y - mu) * inv * gv.y + bv.y);
        u.y = packbf((v.z - mu) * inv * gv.z + bv.z, (v.w - mu) * inv * gv.w + bv.w);
        *(uint2*)(As + r * 136 + lane * 4) = u;
    }
    __syncthreads();

    // load LN'd A fragments once (reused for all 4 chunks)
    uint32_t aAddr = cvta_smem(As + (wid * 16 + (lane & 15)) * 136 + (lane >> 4) * 8);
    uint32_t aA[8][4];
    #pragma unroll
    for (int ks = 0; ks < 8; ks++)
        ldmx4(aA[ks], aAddr + ks * 32u);

    uint32_t w1base = cvta_smem(W1s + (lane & 15) * 136 + (lane >> 4) * 8);
    uint32_t w2base = cvta_smem(W2s + (lane & 15) * 136 + (lane >> 4) * 8);
    int gcol = lane >> 2, t4 = lane & 3;

    float oacc[16][4];
    #pragma unroll
    for (int j = 0; j < 16; j++)
        #pragma unroll
        for (int q = 0; q < 4; q++) oacc[j][q] = 0.0f;

    for (int c = 0; c < 4; c++) {
        CP_WAIT0();
        __syncthreads();
        if (c < 3) {
            __nv_bfloat16* d1 = W1s + ((c + 1) & 1) * 17408;
            __nv_bfloat16* d2 = W2s + ((c + 1) & 1) * 17408;
            const __nv_bfloat16* s1 = W1 + (c + 1) * 128;
            const __nv_bfloat16* s2 = W2 + (size_t)(c + 1) * 128 * 128;
            #pragma unroll
            for (int it = 0; it < 8; it++) {
                int idx = it * 256 + tid;
                int row = idx >> 4, seg = idx & 15;
                cp16(d1 + row * 136 + seg * 8, s1 + row * 512 + seg * 8);
                cp16(d2 + row * 136 + seg * 8, s2 + (size_t)row * 128 + seg * 8);
            }
            CP_COMMIT();
        }

        uint32_t w1a = w1base + (c & 1) * 34816u;
        uint32_t w2a = w2base + (c & 1) * 34816u;

        // phase 1: H-chunk = gelu(A @ W1c + b1c), kept as A-fragments in regs
        uint32_t aH[8][4];
        #pragma unroll
        for (int n2 = 0; n2 < 8; n2++) {
            float h0[4] = {0, 0, 0, 0}, h1[4] = {0, 0, 0, 0};
            #pragma unroll
            for (int ks = 0; ks < 8; ks++) {
                uint32_t r[4];
                ldmx4t(r, w1a + ks * 4352u + n2 * 32u);
                mma16816b(h0, aA[ks], r[0], r[1]);
                mma16816b(h1, aA[ks], r[2], r[3]);
            }
            int cl = c * 128 + n2 * 16 + 2 * t4;
            float b00 = sb1[cl],     b01 = sb1[cl + 1];
            float b10 = sb1[cl + 8], b11 = sb1[cl + 9];
            aH[n2][0] = packbf(gelu_exact(h0[0] + b00), gelu_exact(h0[1] + b01));
            aH[n2][1] = packbf(gelu_exact(h0[2] + b00), gelu_exact(h0[3] + b01));
            aH[n2][2] = packbf(gelu_exact(h1[0] + b10), gelu_exact(h1[1] + b11));
            aH[n2][3] = packbf(gelu_exact(h1[2] + b10), gelu_exact(h1[3] + b11));
        }

        // phase 2: oacc += H-chunk @ W2c  (A from registers)
        #pragma unroll
        for (int ks2 = 0; ks2 < 8; ks2++) {
            #pragma unroll
            for (int no2 = 0; no2 < 8; no2++) {
                uint32_t r[4];
                ldmx4t(r, w2a + ks2 * 4352u + no2 * 32u);
                mma16816b(oacc[no2 * 2],     aH[ks2], r[0], r[1]);
                mma16816b(oacc[no2 * 2 + 1], aH[ks2], r[2], r[3]);
            }
        }
    }

    // epilogue: +b2 + residual y2 -> out fp32
    int r0 = m0 + wid * 16 + gcol, r1 = r0 + 8;
    #pragma unroll
    for (int no = 0; no < 16; no++) {
        int cl = no * 8 + 2 * t4;
        float b0 = sb2[cl], b1v = sb2[cl + 1];
        size_t o0 = (size_t)r0 * 128 + cl;
        size_t o1 = (size_t)r1 * 128 + cl;
        float2 q0 = *(const float2*)(y2 + o0);
        float2 q1 = *(const float2*)(y2 + o1);
        *(float2*)(out + o0) = make_float2(oacc[no][0] + b0 + q0.x,
                                           oacc[no][1] + b1v + q0.y);
        *(float2*)(out + o1) = make_float2(oacc[no][2] + b0 + q1.x,
                                           oacc[no][3] + b1v + q1.y);
    }
}

// ---------------------------------------------------------------------------
extern "C" void kernel_launch(void* const* d_in, const int* in_sizes, int n_in,
                              void* d_out, int out_size) {
    (void)in_sizes; (void)n_in; (void)out_size;
    const float* x       = (const float*)d_in[0];
    const int*   rel_idx = (const int*)  d_in[1];
    const float* rpb     = (const float*)d_in[2];
    const float* qkv_w   = (const float*)d_in[3];
    const float* qkv_b   = (const float*)d_in[4];
    const float* proj_w  = (const float*)d_in[5];
    const float* proj_b  = (const float*)d_in[6];
    const float* ln1_g   = (const float*)d_in[7];
    const float* ln1_b   = (const float*)d_in[8];
    const float* ln2_g   = (const float*)d_in[9];
    const float* ln2_b   = (const float*)d_in[10];
    const float* mlp_w1  = (const float*)d_in[11];
    const float* mlp_b1  = (const float*)d_in[12];
    const float* mlp_w2  = (const float*)d_in[13];
    const float* mlp_b2  = (const float*)d_in[14];
    float* out = (float*)d_out;

    __nv_bfloat16 *qkvb, *ao, *wt;
    float *y2, *btab;
    cudaGetSymbolAddress((void**)&qkvb, g_qkv);
    cudaGetSymbolAddress((void**)&ao,   g_ao);
    cudaGetSymbolAddress((void**)&y2,   g_y2);
    cudaGetSymbolAddress((void**)&wt,   g_wt);
    cudaGetSymbolAddress((void**)&btab, g_btab);
    __nv_bfloat16* wt_qkv = wt;             // [128][384]
    __nv_bfloat16* wt_prj = wt + 49152;     // [128][128]
    __nv_bfloat16* wt_m1  = wt + 65536;     // [128][512]
    __nv_bfloat16* wt_m2  = wt + 131072;    // [512][128]

    cudaFuncSetAttribute(ln_qkv,    cudaFuncAttributeMaxDynamicSharedMemorySize, LQ_SMEM);
    cudaFuncSetAttribute(attn_hmma, cudaFuncAttributeMaxDynamicSharedMemorySize, ASMEM);
    cudaFuncSetAttribute(fused_mlp, cudaFuncAttributeMaxDynamicSharedMemorySize, FM_SMEM);

    prep_all<<<940, 256>>>(qkv_w, proj_w, mlp_w1, mlp_w2, rel_idx, rpb, wt, btab);
    ln_qkv<<<784, 512, LQ_SMEM>>>(x, ln1_g, ln1_b, wt_qkv, qkv_b, qkvb);
    attn_hmma<<<4096, 256, ASMEM>>>(qkvb, btab, ao);
    gemm_proj<<<784, 256>>>(ao, wt_prj, proj_b, x, y2);
    fused_mlp<<<784, 256, FM_SMEM>>>(y2, ln2_g, ln2_b, wt_m1, mlp_b1, wt_m2, mlp_b2, out);
}

// round 10
// speedup vs baseline: 1.1707x; 1.0360x over previous
#include <cuda_runtime.h>
#include <cuda_bf16.h>
#include <math.h>
#include <stdint.h>

// ---------------------------------------------------------------------------
// SwinTransformerBlock3D  (B=4, D=8, H=56, W=56, C=128, WIN=(2,7,7), HEADS=4)
// Kernels: prep | LN1+QKV | attention | proj+res+LN2+MLP1+GELU+MLP2+res
// ---------------------------------------------------------------------------

#define M_TOK 100352            // 4*8*56*56 == 1024 windows * 98 tokens

__device__ __nv_bfloat16 g_qkv[(size_t)M_TOK*384];   // qkv, window order
__device__ __nv_bfloat16 g_ao [(size_t)M_TOK*128];   // attn out, window order
__device__ __nv_bfloat16 g_wt [196608];              // bf16 weights
__device__ float         g_btab[4*98*112];           // log2e * rpb[rel_idx], padded

// window row r -> spatial token (roll -SHIFT folded in); self-inverse mapping.
__device__ __forceinline__ int win_row_to_token(int r) {
    int win = r / 98;
    int n   = r - win * 98;
    int ww = win & 7;
    int wh = (win >> 3) & 7;
    int wd = (win >> 6) & 3;
    int b  = win >> 8;
    int id  = n / 49;
    int rem = n - id * 49;
    int ih  = rem / 7;
    int iw  = rem - ih * 7;
    int d = wd * 2 + id;
    int h = wh * 7 + ih;
    int w = ww * 7 + iw;
    int ds = d + 1;  if (ds >= 8)  ds -= 8;
    int hs = h + 3;  if (hs >= 56) hs -= 56;
    int ws = w + 3;  if (ws >= 56) ws -= 56;
    return ((b * 8 + ds) * 56 + hs) * 56 + ws;
}

// ---------------------------------------------------------------------------
// helpers
// ---------------------------------------------------------------------------
__device__ __forceinline__ uint32_t cvta_smem(const void* p) {
    uint32_t a;
    asm("{ .reg .u64 t; cvta.to.shared.u64 t, %1; cvt.u32.u64 %0, t; }"
        : "=r"(a) : "l"(p));
    return a;
}
__device__ __forceinline__ uint32_t packbf(float a, float b) {
    __nv_bfloat162 t = __floats2bfloat162_rn(a, b);
    return *reinterpret_cast<uint32_t*>(&t);
}
__device__ __forceinline__ void ldmx4(uint32_t* r, uint32_t addr) {
    asm volatile("ldmatrix.sync.aligned.m8n8.x4.shared.b16 {%0,%1,%2,%3}, [%4];"
        : "=r"(r[0]), "=r"(r[1]), "=r"(r[2]), "=r"(r[3]) : "r"(addr));
}
__device__ __forceinline__ void ldmx4t(uint32_t* r, uint32_t addr) {
    asm volatile("ldmatrix.sync.aligned.m8n8.x4.trans.shared.b16 {%0,%1,%2,%3}, [%4];"
        : "=r"(r[0]), "=r"(r[1]), "=r"(r[2]), "=r"(r[3]) : "r"(addr));
}
__device__ __forceinline__ void mma16816(float* d, const uint32_t* a, const uint32_t* b) {
    asm volatile("mma.sync.aligned.m16n8k16.row.col.f32.bf16.bf16.f32 "
        "{%0,%1,%2,%3}, {%4,%5,%6,%7}, {%8,%9}, {%0,%1,%2,%3};"
        : "+f"(d[0]), "+f"(d[1]), "+f"(d[2]), "+f"(d[3])
        : "r"(a[0]), "r"(a[1]), "r"(a[2]), "r"(a[3]), "r"(b[0]), "r"(b[1]));
}
__device__ __forceinline__ void mma16816b(float* d, const uint32_t* a,
                                          uint32_t b0, uint32_t b1) {
    asm volatile("mma.sync.aligned.m16n8k16.row.col.f32.bf16.bf16.f32 "
        "{%0,%1,%2,%3}, {%4,%5,%6,%7}, {%8,%9}, {%0,%1,%2,%3};"
        : "+f"(d[0]), "+f"(d[1]), "+f"(d[2]), "+f"(d[3])
        : "r"(a[0]), "r"(a[1]), "r"(a[2]), "r"(a[3]), "r"(b0), "r"(b1));
}
__device__ __forceinline__ void cp16(const void* smem_dst, const void* gsrc) {
    uint32_t d = cvta_smem(smem_dst);
    asm volatile("cp.async.cg.shared.global [%0], [%1], 16;" :: "r"(d), "l"(gsrc));
}
#define CP_COMMIT()  asm volatile("cp.async.commit_group;" ::: "memory")
#define CP_WAIT0()   asm volatile("cp.async.wait_group 0;" ::: "memory")
__device__ __forceinline__ float gelu_exact(float v) {
    return 0.5f * v * (1.0f + erff(v * 0.7071067811865476f));
}

// ---------------------------------------------------------------------------
// Single prep kernel: 4 weight casts + bias table
// ---------------------------------------------------------------------------
__global__ void prep_all(const float* __restrict__ qkv_w, const float* __restrict__ proj_w,
                         const float* __restrict__ mlp_w1, const float* __restrict__ mlp_w2,
                         const int* __restrict__ rel_idx, const float* __restrict__ rpb,
                         __nv_bfloat16* __restrict__ wt, float* __restrict__ btab) {
    int i = blockIdx.x * 256 + threadIdx.x;
    if (i < 49152) { wt[i] = __float2bfloat16(qkv_w[i]); return; }
    i -= 49152;
    if (i < 16384) { wt[49152 + i] = __float2bfloat16(proj_w[i]); return; }
    i -= 16384;
    if (i < 65536) { wt[65536 + i] = __float2bfloat16(mlp_w1[i]); return; }
    i -= 65536;
    if (i < 65536) { wt[131072 + i] = __float2bfloat16(mlp_w2[i]); return; }
    i -= 65536;
    if (i < 4 * 98 * 112) {
        int h = i / 10976, rem = i - h * 10976;
        int row = rem / 112, col = rem - row * 112;
        float v = 0.0f;
        if (col < 98) v = rpb[rel_idx[row * 98 + col] * 4 + h] * 1.4426950408889634f;
        btab[i] = v;
    }
}

// ---------------------------------------------------------------------------
// Fused LN1(gather) + QKV GEMM. 512 threads, 16 warps (4x4, 32x32 tiles).
// ---------------------------------------------------------------------------
#define LQ_AS 0
#define LQ_BS 34816
#define LQ_SB 104448              // 384 floats
#define LQ_SMEM (104448 + 1536)   // 105984

__global__ __launch_bounds__(512, 2)
void ln_qkv(const float* __restrict__ x, const float* __restrict__ g,
            const float* __restrict__ beta, const __nv_bfloat16* __restrict__ W,
            const float* __restrict__ bias, __nv_bfloat16* __restrict__ qkv) {
    extern __shared__ char smc[];
    __nv_bfloat16* As = (__nv_bfloat16*)(smc + LQ_AS);
    __nv_bfloat16* Bs = (__nv_bfloat16*)(smc + LQ_BS);
    float*         sb = (float*)(smc + LQ_SB);

    int tid = threadIdx.x, lane = tid & 31, wid = tid >> 5;
    int wm = wid & 3, wn = wid >> 2;
    int m0 = blockIdx.x * 128;

    #pragma unroll
    for (int it = 0; it < 4; it++) {
        int idx = it * 512 + tid;
        int row = idx >> 4, seg = idx & 15;
        cp16(Bs + row * 136 + seg * 8, W + row * 384 + seg * 8);
    }
    CP_COMMIT();
    if (tid < 384) sb[tid] = bias[tid];

    #pragma unroll
    for (int i = 0; i < 8; i++) {
        int r = i * 16 + wid;
        int src = win_row_to_token(m0 + r);
        float4 v = *(const float4*)(x + (size_t)src * 128 + lane * 4);
        float s  = v.x + v.y + v.z + v.w;
        float s2 = fmaf(v.x, v.x, fmaf(v.y, v.y, fmaf(v.z, v.z, v.w * v.w)));
        #pragma unroll
        for (int o = 16; o; o >>= 1) {
            s  += __shfl_xor_sync(0xffffffffu, s,  o);
            s2 += __shfl_xor_sync(0xffffffffu, s2, o);
        }
        float mu  = s * (1.0f / 128.0f);
        float var = s2 * (1.0f / 128.0f) - mu * mu;
        float inv = rsqrtf(var + 1e-5f);
        float4 gv = *(const float4*)(g + lane * 4);
        float4 bv = *(const float4*)(beta + lane * 4);
        uint2 u;
        u.x = packbf((v.x - mu) * inv * gv.x + bv.x, (v.y - mu) * inv * gv.y + bv.y);
        u.y = packbf((v.z - mu) * inv * gv.z + bv.z, (v.w - mu) * inv * gv.w + bv.w);
        *(uint2*)(As + r * 136 + lane * 4) = u;
    }

    uint32_t aAddr  = cvta_smem(As + (wm * 32 + (lane & 15)) * 136 + (lane >> 4) * 8);
    uint32_t bAddr0 = cvta_smem(Bs + (lane & 15) * 136 + wn * 32 + (lane >> 4) * 8);
    int gcol = lane >> 2, t4 = lane & 3;

    for (int c = 0; c < 3; c++) {
        CP_WAIT0();
        __syncthreads();
        if (c < 2) {
            __nv_bfloat16* dst = Bs + ((c + 1) & 1) * 17408;
            const __nv_bfloat16* src = W + (c + 1) * 128;
            #pragma unroll
            for (int it = 0; it < 4; it++) {
                int idx = it * 512 + tid;
                int row = idx >> 4, seg = idx & 15;
                cp16(dst + row * 136 + seg * 8, src + row * 384 + seg * 8);
            }
            CP_COMMIT();
        }

        float acc[2][4][4];
        #pragma unroll
        for (int mi = 0; mi < 2; mi++)
            #pragma unroll
            for (int ni = 0; ni < 4; ni++)
                #pragma unroll
                for (int q = 0; q < 4; q++) acc[mi][ni][q] = 0.0f;

        uint32_t bAddr = bAddr0 + (c & 1) * 34816u;
        #pragma unroll
        for (int s = 0; s < 8; s++) {
            uint32_t aF[2][4];
            #pragma unroll
            for (int mi = 0; mi < 2; mi++)
                ldmx4(aF[mi], aAddr + mi * 4352u + s * 32u);
            uint32_t bF[4][2];
            #pragma unroll
            for (int nq = 0; nq < 2; nq++) {
                uint32_t r[4];
                ldmx4t(r, bAddr + s * 4352u + nq * 32u);
                bF[2 * nq    ][0] = r[0]; bF[2 * nq    ][1] = r[1];
                bF[2 * nq + 1][0] = r[2]; bF[2 * nq + 1][1] = r[3];
            }
            #pragma unroll
            for (int mi = 0; mi < 2; mi++)
                #pragma unroll
                for (int ni = 0; ni < 4; ni++)
                    mma16816(acc[mi][ni], aF[mi], bF[ni]);
        }

        #pragma unroll
        for (int mi = 0; mi < 2; mi++) {
            int rl = wm * 32 + mi * 16 + gcol;
            #pragma unroll
            for (int ni = 0; ni < 4; ni++) {
                int cl = wn * 32 + ni * 8 + t4 * 2;
                float b0 = sb[c * 128 + cl], b1 = sb[c * 128 + cl + 1];
                *(uint32_t*)(qkv + (size_t)(m0 + rl) * 384 + c * 128 + cl) =
                    packbf(acc[mi][ni][0] + b0, acc[mi][ni][1] + b1);
                *(uint32_t*)(qkv + (size_t)(m0 + rl + 8) * 384 + c * 128 + cl) =
                    packbf(acc[mi][ni][2] + b0, acc[mi][ni][3] + b1);
            }
        }
        __syncthreads();
    }
}

// ---------------------------------------------------------------------------
// HMMA attention: one block per (window, head), 256 threads (8 warps x 16 rows).
// ---------------------------------------------------------------------------
#define ASMEM 30720

__global__ __launch_bounds__(256)
void attn_hmma(const __nv_bfloat16* __restrict__ qkv, const float* __restrict__ btab,
               __nv_bfloat16* __restrict__ ao) {
    extern __shared__ char smc[];
    __nv_bfloat16* Qs = (__nv_bfloat16*)(smc);
    __nv_bfloat16* Ks = (__nv_bfloat16*)(smc + 10240);
    __nv_bfloat16* Vs = (__nv_bfloat16*)(smc + 20480);

    int tid = threadIdx.x, warp = tid >> 5, lane = tid & 31;
    int g = lane >> 2, t4 = lane & 3;
    int win = blockIdx.x >> 2, head = blockIdx.x & 3;
    const float CEXP = 0.17677669529663687f * 1.4426950408889634f;
    const float* bt = btab + head * 10976;

    #pragma unroll
    for (int it = 0; it < 2; it++) {
        int idx = it * 256 + tid;
        int row = idx >> 2, seg = idx & 3;
        uint4 zq = make_uint4(0, 0, 0, 0), zk = zq, zv = zq;
        if (row < 98) {
            const __nv_bfloat16* base = qkv + (size_t)(win * 98 + row) * 384 + head * 32 + seg * 8;
            zq = *(const uint4*)(base);
            zk = *(const uint4*)(base + 128);
            zv = *(const uint4*)(base + 256);
        }
        *(uint4*)(Qs + row * 40 + seg * 8) = zq;
        *(uint4*)(Ks + row * 40 + seg * 8) = zk;
        *(uint4*)(Vs + row * 40 + seg * 8) = zv;
    }
    __syncthreads();

    uint32_t qAddr = cvta_smem(Qs + (warp * 16 + (lane & 15)) * 40 + (lane >> 4) * 8);
    uint32_t kAddr = cvta_smem(Ks + (lane & 15) * 40 + (lane >> 4) * 8);
    uint32_t vAddr = cvta_smem(Vs + (lane & 15) * 40 + (lane >> 4) * 8);

    float sacc[13][4];
    #pragma unroll
    for (int j = 0; j < 13; j++)
        #pragma unroll
        for (int q = 0; q < 4; q++) sacc[j][q] = 0.0f;

    #pragma unroll
    for (int ks = 0; ks < 32; ks += 16) {
        uint32_t aF[4];
        ldmx4(aF, qAddr + ks * 2u);
        #pragma unroll
        for (int j2 = 0; j2 < 7; j2++) {
            uint32_t r[4];
            ldmx4(r, kAddr + j2 * 1280u + ks * 2u);
            mma16816b(sacc[2 * j2], aF, r[0], r[2]);
            if (j2 < 6) mma16816b(sacc[2 * j2 + 1], aF, r[1], r[3]);
        }
    }

    int ra = warp * 16 + g, rb = ra + 8;
    bool oka = ra < 98, okb = rb < 98;
    float rsum0 = 0.0f, rsum1 = 0.0f;
    #pragma unroll
    for (int j = 0; j < 13; j++) {
        int c0 = 8 * j + 2 * t4;
        bool cv = c0 < 98;
        float e0 = 0.0f, e1 = 0.0f, e2 = 0.0f, e3 = 0.0f;
        if (cv && oka) {
            float2 bb = *(const float2*)(bt + ra * 112 + c0);
            e0 = exp2f(fmaf(sacc[j][0], CEXP, bb.x));
            e1 = exp2f(fmaf(sacc[j][1], CEXP, bb.y));
        }
        if (cv && okb) {
            float2 bb = *(const float2*)(bt + rb * 112 + c0);
            e2 = exp2f(fmaf(sacc[j][2], CEXP, bb.x));
            e3 = exp2f(fmaf(sacc[j][3], CEXP, bb.y));
        }
        sacc[j][0] = e0; sacc[j][1] = e1; sacc[j][2] = e2; sacc[j][3] = e3;
        rsum0 += e0 + e1;
        rsum1 += e2 + e3;
    }
    rsum0 += __shfl_xor_sync(0xffffffffu, rsum0, 1);
    rsum0 += __shfl_xor_sync(0xffffffffu, rsum0, 2);
    rsum1 += __shfl_xor_sync(0xffffffffu, rsum1, 1);
    rsum1 += __shfl_xor_sync(0xffffffffu, rsum1, 2);
    float inv0 = 1.0f / rsum0, inv1 = 1.0f / rsum1;

    float oacc[4][4];
    #pragma unroll
    for (int j = 0; j < 4; j++)
        #pragma unroll
        for (int q = 0; q < 4; q++) oacc[j][q] = 0.0f;

    #pragma unroll
    for (int ks2 = 0; ks2 < 7; ks2++) {
        uint32_t bV[4][2];
        #pragma unroll
        for (int nq = 0; nq < 2; nq++) {
            uint32_t r[4];
            ldmx4t(r, vAddr + ks2 * 1280u + nq * 32u);
            bV[2 * nq    ][0] = r[0]; bV[2 * nq    ][1] = r[1];
            bV[2 * nq + 1][0] = r[2]; bV[2 * nq + 1][1] = r[3];
        }
        uint32_t a[4];
        a[0] = packbf(sacc[2 * ks2][0], sacc[2 * ks2][1]);
        a[1] = packbf(sacc[2 * ks2][2], sacc[2 * ks2][3]);
        if (ks2 < 6) {
            a[2] = packbf(sacc[2 * ks2 + 1][0], sacc[2 * ks2 + 1][1]);
            a[3] = packbf(sacc[2 * ks2 + 1][2], sacc[2 * ks2 + 1][3]);
        } else { a[2] = 0u; a[3] = 0u; }
        #pragma unroll
        for (int j = 0; j < 4; j++)
            mma16816(oacc[j], a, bV[j]);
    }

    #pragma unroll
    for (int j = 0; j < 4; j++) {
        int c = head * 32 + 8 * j + 2 * t4;
        if (oka)
            *(uint32_t*)(ao + (size_t)(win * 98 + ra) * 128 + c) =
                packbf(oacc[j][0] * inv0, oacc[j][1] * inv0);
        if (okb)
            *(uint32_t*)(ao + (size_t)(win * 98 + rb) * 128 + c) =
                packbf(oacc[j][2] * inv1, oacc[j][3] * inv1);
    }
}

// ---------------------------------------------------------------------------
// MEGA-FUSED: proj + bias + x-residual + LN2 + MLP1 + GELU + MLP2 + residual.
// 256 threads, 8 warps, m-split (warp = 16 rows x all cols).
// Proj acc fragments -> (residual, LN via quad shuffles) -> MLP A-fragments
// in registers. y2 parked in smem only for the final residual.
// smem region R (139264B): proj: Ao[0..34816]+Wp[34816..69632];
//                          MLP:  W1 dbl [0..69632] + W2 dbl [69632..139264]
// ---------------------------------------------------------------------------
#define FP_W2D  69632
#define FP_Y2S  139264               // float[128][132]
#define FP_BP   206848               // 128 f
#define FP_B1   207360               // 512 f
#define FP_B2   209408               // 128 f
#define FP_LNG  209920               // 128 f
#define FP_LNB  210432               // 128 f
#define FP_SMEM 210944

__global__ __launch_bounds__(256, 1)
void fused_proj_mlp(const __nv_bfloat16* __restrict__ Ao, const __nv_bfloat16* __restrict__ Wp,
                    const float* __restrict__ bp, const float* __restrict__ x,
                    const float* __restrict__ lng, const float* __restrict__ lnb,
                    const __nv_bfloat16* __restrict__ W1, const float* __restrict__ b1,
                    const __nv_bfloat16* __restrict__ W2, const float* __restrict__ b2,
                    float* __restrict__ out) {
    extern __shared__ char smc[];
    __nv_bfloat16* AoS = (__nv_bfloat16*)(smc);
    __nv_bfloat16* WpS = (__nv_bfloat16*)(smc + 34816);
    __nv_bfloat16* W1s = (__nv_bfloat16*)(smc);            // reuse after proj
    __nv_bfloat16* W2s = (__nv_bfloat16*)(smc + FP_W2D);
    float* y2s = (float*)(smc + FP_Y2S);
    float* sbp = (float*)(smc + FP_BP);
    float* sb1 = (float*)(smc + FP_B1);
    float* sb2 = (float*)(smc + FP_B2);
    float* slg = (float*)(smc + FP_LNG);
    float* slb = (float*)(smc + FP_LNB);
    __shared__ int rowmap[128];

    int tid = threadIdx.x, lane = tid & 31, wid = tid >> 5;
    int gq = lane >> 2, t4 = lane & 3;
    int m0 = blockIdx.x * 128;

    // stage Ao tile + Wp
    #pragma unroll
    for (int it = 0; it < 8; it++) {
        int idx = it * 256 + tid;
        int row = idx >> 4, seg = idx & 15;
        cp16(AoS + row * 136 + seg * 8, Ao + (size_t)(m0 + row) * 128 + seg * 8);
        cp16(WpS + row * 136 + seg * 8, Wp + (size_t)row * 128 + seg * 8);
    }
    CP_COMMIT();
    if (tid < 128) {
        sbp[tid] = bp[tid];
        sb2[tid] = b2[tid];
        slg[tid] = lng[tid];
        slb[tid] = lnb[tid];
        rowmap[tid] = win_row_to_token(m0 + tid);
    }
    sb1[tid] = b1[tid];
    sb1[256 + tid] = b1[256 + tid];

    uint32_t aoAddr = cvta_smem(AoS + (wid * 16 + (lane & 15)) * 136 + (lane >> 4) * 8);
    uint32_t wpBase = cvta_smem(WpS + (lane & 15) * 136 + (lane >> 4) * 8);

    CP_WAIT0();
    __syncthreads();

    // ---- proj: pacc[16][4] = Ao(16 rows) @ Wp(128x128) ----
    uint32_t aAo[8][4];
    #pragma unroll
    for (int ks = 0; ks < 8; ks++)
        ldmx4(aAo[ks], aoAddr + ks * 32u);

    float pacc[16][4];
    #pragma unroll
    for (int j = 0; j < 16; j++)
        #pragma unroll
        for (int q = 0; q < 4; q++) pacc[j][q] = 0.0f;

    #pragma unroll
    for (int ks = 0; ks < 8; ks++) {
        #pragma unroll
        for (int n2 = 0; n2 < 8; n2++) {
            uint32_t r[4];
            ldmx4t(r, wpBase + ks * 4352u + n2 * 32u);
            mma16816b(pacc[2 * n2],     aAo[ks], r[0], r[1]);
            mma16816b(pacc[2 * n2 + 1], aAo[ks], r[2], r[3]);
        }
    }
    __syncthreads();   // all warps done reading AoS/WpS

    // prefetch W1/W2 chunk 0 into reused region (overlaps LN math below)
    #pragma unroll
    for (int it = 0; it < 8; it++) {
        int idx = it * 256 + tid;
        int row = idx >> 4, seg = idx & 15;
        cp16(W1s + row * 136 + seg * 8, W1 + row * 512 + seg * 8);
        cp16(W2s + row * 136 + seg * 8, W2 + (size_t)row * 128 + seg * 8);
    }
    CP_COMMIT();

    // ---- y2 = pacc + bias + x (gathered); LN stats via quad shuffles ----
    int ra = wid * 16 + gq, rb = ra + 8;
    int rowA = rowmap[ra], rowB = rowmap[rb];
    float s0 = 0.0f, q0 = 0.0f, s1 = 0.0f, q1 = 0.0f;
    #pragma unroll
    for (int j = 0; j < 16; j++) {
        int cl = 8 * j + 2 * t4;
        float2 bv = *(const float2*)(sbp + cl);
        float2 xa = *(const float2*)(x + (size_t)rowA * 128 + cl);
        float2 xb = *(const float2*)(x + (size_t)rowB * 128 + cl);
        pacc[j][0] += bv.x + xa.x;  pacc[j][1] += bv.y + xa.y;
        pacc[j][2] += bv.x + xb.x;  pacc[j][3] += bv.y + xb.y;
        s0 += pacc[j][0] + pacc[j][1];
        q0 = fmaf(pacc[j][0], pacc[j][0], fmaf(pacc[j][1], pacc[j][1], q0));
        s1 += pacc[j][2] + pacc[j][3];
        q1 = fmaf(pacc[j][2], pacc[j][2], fmaf(pacc[j][3], pacc[j][3], q1));
        *(float2*)(y2s + ra * 132 + cl) = make_float2(pacc[j][0], pacc[j][1]);
        *(float2*)(y2s + rb * 132 + cl) = make_float2(pacc[j][2], pacc[j][3]);
    }
    s0 += __shfl_xor_sync(0xffffffffu, s0, 1);
    s0 += __shfl_xor_sync(0xffffffffu, s0, 2);
    q0 += __shfl_xor_sync(0xffffffffu, q0, 1);
    q0 += __shfl_xor_sync(0xffffffffu, q0, 2);
    s1 += __shfl_xor_sync(0xffffffffu, s1, 1);
    s1 += __shfl_xor_sync(0xffffffffu, s1, 2);
    q1 += __shfl_xor_sync(0xffffffffu, q1, 1);
    q1 += __shfl_xor_sync(0xffffffffu, q1, 2);
    float mu0 = s0 * (1.0f / 128.0f);
    float iv0 = rsqrtf(q0 * (1.0f / 128.0f) - mu0 * mu0 + 1e-5f);
    float mu1 = s1 * (1.0f / 128.0f);
    float iv1 = rsqrtf(q1 * (1.0f / 128.0f) - mu1 * mu1 + 1e-5f);

    // LN'd values as MLP A-fragments (register-resident, reused all 4 chunks)
    uint32_t aA[8][4];
    #pragma unroll
    for (int ks = 0; ks < 8; ks++) {
        int c0 = 16 * ks + 2 * t4;
        float2 g0 = *(const float2*)(slg + c0),     e0 = *(const float2*)(slb + c0);
        float2 g1 = *(const float2*)(slg + c0 + 8), e1 = *(const float2*)(slb + c0 + 8);
        aA[ks][0] = packbf((pacc[2*ks][0]   - mu0) * iv0 * g0.x + e0.x,
                           (pacc[2*ks][1]   - mu0) * iv0 * g0.y + e0.y);
        aA[ks][1] = packbf((pacc[2*ks][2]   - mu1) * iv1 * g0.x + e0.x,
                           (pacc[2*ks][3]   - mu1) * iv1 * g0.y + e0.y);
        aA[ks][2] = packbf((pacc[2*ks+1][0] - mu0) * iv0 * g1.x + e1.x,
                           (pacc[2*ks+1][1] - mu0) * iv0 * g1.y + e1.y);
        aA[ks][3] = packbf((pacc[2*ks+1][2] - mu1) * iv1 * g1.x + e1.x,
                           (pacc[2*ks+1][3] - mu1) * iv1 * g1.y + e1.y);
    }

    uint32_t w1base = cvta_smem(W1s + (lane & 15) * 136 + (lane >> 4) * 8);
    uint32_t w2base = cvta_smem(W2s + (lane & 15) * 136 + (lane >> 4) * 8);

    float oacc[16][4];
    #pragma unroll
    for (int j = 0; j < 16; j++)
        #pragma unroll
        for (int q = 0; q < 4; q++) oacc[j][q] = 0.0f;

    for (int c = 0; c < 4; c++) {
        CP_WAIT0();
        __syncthreads();
        if (c < 3) {
            __nv_bfloat16* d1 = W1s + ((c + 1) & 1) * 17408;
            __nv_bfloat16* d2 = W2s + ((c + 1) & 1) * 17408;
            const __nv_bfloat16* s1p = W1 + (c + 1) * 128;
            const __nv_bfloat16* s2p = W2 + (size_t)(c + 1) * 128 * 128;
            #pragma unroll
            for (int it = 0; it < 8; it++) {
                int idx = it * 256 + tid;
                int row = idx >> 4, seg = idx & 15;
                cp16(d1 + row * 136 + seg * 8, s1p + row * 512 + seg * 8);
                cp16(d2 + row * 136 + seg * 8, s2p + (size_t)row * 128 + seg * 8);
            }
            CP_COMMIT();
        }

        uint32_t w1a = w1base + (c & 1) * 34816u;
        uint32_t w2a = w2base + (c & 1) * 34816u;

        // phase 1: H-chunk = gelu(A @ W1c + b1c) as A-fragments in regs
        uint32_t aH[8][4];
        #pragma unroll
        for (int n2 = 0; n2 < 8; n2++) {
            float h0[4] = {0, 0, 0, 0}, h1[4] = {0, 0, 0, 0};
            #pragma unroll
            for (int ks = 0; ks < 8; ks++) {
                uint32_t r[4];
                ldmx4t(r, w1a + ks * 4352u + n2 * 32u);
                mma16816b(h0, aA[ks], r[0], r[1]);
                mma16816b(h1, aA[ks], r[2], r[3]);
            }
            int cl = c * 128 + n2 * 16 + 2 * t4;
            float b00 = sb1[cl],     b01 = sb1[cl + 1];
            float b10 = sb1[cl + 8], b11 = sb1[cl + 9];
            aH[n2][0] = packbf(gelu_exact(h0[0] + b00), gelu_exact(h0[1] + b01));
            aH[n2][1] = packbf(gelu_exact(h0[2] + b00), gelu_exact(h0[3] + b01));
            aH[n2][2] = packbf(gelu_exact(h1[0] + b10), gelu_exact(h1[1] + b11));
            aH[n2][3] = packbf(gelu_exact(h1[2] + b10), gelu_exact(h1[3] + b11));
        }

        // phase 2: oacc += H-chunk @ W2c
        #pragma unroll
        for (int ks2 = 0; ks2 < 8; ks2++) {
            #pragma unroll
            for (int no2 = 0; no2 < 8; no2++) {
                uint32_t r[4];
                ldmx4t(r, w2a + ks2 * 4352u + no2 * 32u);
                mma16816b(oacc[no2 * 2],     aH[ks2], r[0], r[1]);
                mma16816b(oacc[no2 * 2 + 1], aH[ks2], r[2], r[3]);
            }
        }
    }

    // epilogue: +b2 + y2 residual (smem), scatter to spatial rows
    #pragma unroll
    for (int no = 0; no < 16; no++) {
        int cl = no * 8 + 2 * t4;
        float b0 = sb2[cl], b1v = sb2[cl + 1];
        float2 ya = *(const float2*)(y2s + ra * 132 + cl);
        float2 yb = *(const float2*)(y2s + rb * 132 + cl);
        *(float2*)(out + (size_t)rowA * 128 + cl) =
            make_float2(oacc[no][0] + b0 + ya.x, oacc[no][1] + b1v + ya.y);
        *(float2*)(out + (size_t)rowB * 128 + cl) =
            make_float2(oacc[no][2] + b0 + yb.x, oacc[no][3] + b1v + yb.y);
    }
}

// ---------------------------------------------------------------------------
extern "C" void kernel_launch(void* const* d_in, const int* in_sizes, int n_in,
                              void* d_out, int out_size) {
    (void)in_sizes; (void)n_in; (void)out_size;
    const float* x       = (const float*)d_in[0];
    const int*   rel_idx = (const int*)  d_in[1];
    const float* rpb     = (const float*)d_in[2];
    const float* qkv_w   = (const float*)d_in[3];
    const float* qkv_b   = (const float*)d_in[4];
    const float* proj_w  = (const float*)d_in[5];
    const float* proj_b  = (const float*)d_in[6];
    const float* ln1_g   = (const float*)d_in[7];
    const float* ln1_b   = (const float*)d_in[8];
    const float* ln2_g   = (const float*)d_in[9];
    const float* ln2_b   = (const float*)d_in[10];
    const float* mlp_w1  = (const float*)d_in[11];
    const float* mlp_b1  = (const float*)d_in[12];
    const float* mlp_w2  = (const float*)d_in[13];
    const float* mlp_b2  = (const float*)d_in[14];
    float* out = (float*)d_out;

    __nv_bfloat16 *qkvb, *ao, *wt;
    float *btab;
    cudaGetSymbolAddress((void**)&qkvb, g_qkv);
    cudaGetSymbolAddress((void**)&ao,   g_ao);
    cudaGetSymbolAddress((void**)&wt,   g_wt);
    cudaGetSymbolAddress((void**)&btab, g_btab);
    __nv_bfloat16* wt_qkv = wt;             // [128][384]
    __nv_bfloat16* wt_prj = wt + 49152;     // [128][128]
    __nv_bfloat16* wt_m1  = wt + 65536;     // [128][512]
    __nv_bfloat16* wt_m2  = wt + 131072;    // [512][128]

    cudaFuncSetAttribute(ln_qkv,         cudaFuncAttributeMaxDynamicSharedMemorySize, LQ_SMEM);
    cudaFuncSetAttribute(attn_hmma,      cudaFuncAttributeMaxDynamicSharedMemorySize, ASMEM);
    cudaFuncSetAttribute(fused_proj_mlp, cudaFuncAttributeMaxDynamicSharedMemorySize, FP_SMEM);

    prep_all<<<940, 256>>>(qkv_w, proj_w, mlp_w1, mlp_w2, rel_idx, rpb, wt, btab);
    ln_qkv<<<784, 512, LQ_SMEM>>>(x, ln1_g, ln1_b, wt_qkv, qkv_b, qkvb);
    attn_hmma<<<4096, 256, ASMEM>>>(qkvb, btab, ao);
    fused_proj_mlp<<<784, 256, FP_SMEM>>>(ao, wt_prj, proj_b, x, ln2_g, ln2_b,
                                          wt_m1, mlp_b1, wt_m2, mlp_b2, out);
}